// round 11
// baseline (speedup 1.0000x reference)
#include <cuda_runtime.h>
#include <cuda_bf16.h>
#include <stdint.h>

#define BD 16
#define TD 256
#define HD 128
#define VD 50000
#define VPAD 50048
#define NROW 4096              // B*T
#define GDIM 512               // 4*H
#define HOFF 204800000l        // start of h in out (16*256*50000)
#define COFF 204804096l        // start of c in out

// ------------------------- scratch (device globals) ------------------------
__device__ float g_xp0[NROW * GDIM];
__device__ float g_xp1[NROW * GDIM];
__device__ float g_y0[NROW * HD];
__device__ float g_y1[NROW * HD];
__device__ __nv_bfloat16 g_A3[NROW * 384];   // [b*256+t][384] (hi|lo|hi)
__device__ __nv_bfloat16 g_B3[VPAD * 384];   // [v][384]       (hi|hi|lo)
__device__ int g_flags0[NROW * 2];
__device__ int g_flags1[NROW * 2];

// ------------------------------ zero flags ---------------------------------
__global__ void zero_flags_kernel() {
    int i = blockIdx.x * 256 + threadIdx.x;
    if (i < NROW * 2) { g_flags0[i] = 0; g_flags1[i] = 0; }
}

// ---------------- projection GEMM: out[r][g] = A[r] . W[g] + b1[g]+b2[g] ----
// A row r (= t*16+b) is emb[x[b][t]] when xids != 0, else Arows + r*128.
__global__ __launch_bounds__(256) void proj_kernel(
    const float* __restrict__ Arows, const int* __restrict__ xids,
    const float* __restrict__ emb, const float* __restrict__ W,
    const float* __restrict__ b1, const float* __restrict__ b2,
    float* __restrict__ outp)
{
    __shared__ float Asm[64][65];   // [k][m]
    __shared__ float Bsm[64][65];   // [k][g]
    const int tb0 = blockIdx.y * 64;
    const int g0  = blockIdx.x * 64;
    const int tid = threadIdx.x;
    const int tx = tid & 15, ty = tid >> 4;
    float acc[4][4] = {};

    for (int kc = 0; kc < 128; kc += 64) {
        for (int i = tid; i < 64 * 64; i += 256) {
            int m = i >> 6, k = i & 63;
            int r = tb0 + m;
            const float* ar;
            if (xids) ar = emb + (size_t)xids[(r & 15) * 256 + (r >> 4)] * 128;
            else      ar = Arows + (size_t)r * 128;
            Asm[k][m] = ar[kc + k];
        }
        for (int i = tid; i < 64 * 64; i += 256) {
            int n = i >> 6, k = i & 63;
            Bsm[k][n] = W[(size_t)(g0 + n) * 128 + kc + k];
        }
        __syncthreads();
#pragma unroll 16
        for (int k = 0; k < 64; k++) {
            float a[4], bb[4];
#pragma unroll
            for (int i = 0; i < 4; i++) a[i] = Asm[k][ty * 4 + i];
#pragma unroll
            for (int j = 0; j < 4; j++) bb[j] = Bsm[k][tx * 4 + j];
#pragma unroll
            for (int i = 0; i < 4; i++)
#pragma unroll
                for (int j = 0; j < 4; j++) acc[i][j] += a[i] * bb[j];
        }
        __syncthreads();
    }
#pragma unroll
    for (int i = 0; i < 4; i++) {
        int r = tb0 + ty * 4 + i;
#pragma unroll
        for (int j = 0; j < 4; j++) {
            int g = g0 + tx * 4 + j;
            outp[(size_t)r * GDIM + g] = acc[i][j] + b1[g] + b2[g];
        }
    }
}

// --------------------------- LSTM layer (persistent) -----------------------
// 32 CTAs: b = blk>>1, half = blk&1. 256 threads. Thread owns one W_hh row
// (gate*128 + half*64 + u) register-resident. Cross-CTA h exchange via y +
// per-step flags in global memory.
__device__ __forceinline__ float sigmoidf_(float x) {
    return 1.0f / (1.0f + __expf(-x));
}

__global__ __launch_bounds__(256, 1) void lstm_kernel(
    const float* __restrict__ xp, const float* __restrict__ Whh,
    float* __restrict__ y, int* flags, float* __restrict__ outp, int layer)
{
    const int b = blockIdx.x >> 1;
    const int half = blockIdx.x & 1;
    const int tid = threadIdx.x;
    const int u = tid & 63, gate = tid >> 6;
    const int row = gate * 128 + half * 64 + u;

    __shared__ __align__(16) float h_sm[128];
    __shared__ float gates_sm[256];

    float w[128];
#pragma unroll
    for (int k = 0; k < 128; k++) w[k] = Whh[(size_t)row * 128 + k];

    if (tid < 128) h_sm[tid] = 0.0f;
    float c = 0.0f;
    __syncthreads();

    for (int t = 0; t < TD; t++) {
        const size_t rbase = (size_t)(t * 16 + b);
        float xv = xp[rbase * GDIM + row];

        float a0 = 0.f, a1 = 0.f, a2 = 0.f, a3 = 0.f;
        const float4* h4 = (const float4*)h_sm;
#pragma unroll
        for (int k = 0; k < 32; k++) {
            float4 hv = h4[k];
            a0 += w[4 * k + 0] * hv.x;
            a1 += w[4 * k + 1] * hv.y;
            a2 += w[4 * k + 2] * hv.z;
            a3 += w[4 * k + 3] * hv.w;
        }
        gates_sm[tid] = xv + (a0 + a1) + (a2 + a3);
        __syncthreads();

        if (tid < 64) {
            float i_ = sigmoidf_(gates_sm[tid]);
            float f_ = sigmoidf_(gates_sm[64 + tid]);
            float g_ = tanhf(gates_sm[128 + tid]);
            float o_ = sigmoidf_(gates_sm[192 + tid]);
            c = f_ * c + i_ * g_;
            float h = o_ * tanhf(c);
            int gu = half * 64 + tid;
            h_sm[gu] = h;
            __stcg(&y[rbase * HD + gu], h);
            if (t == TD - 1) {
                outp[HOFF + (size_t)layer * 2048 + b * 128 + gu] = h;
                outp[COFF + (size_t)layer * 2048 + b * 128 + gu] = c;
            }
        }
        __threadfence();
        __syncthreads();

        const int fbase = (int)rbase * 2;
        if (tid == 0) {
            *((volatile int*)&flags[fbase + half]) = 1;
            while (*((volatile int*)&flags[fbase + (half ^ 1)]) == 0) {}
        }
        __syncthreads();
        if (tid < 64)
            h_sm[(half ^ 1) * 64 + tid] =
                __ldcg(&y[rbase * HD + (half ^ 1) * 64 + tid]);
        __syncthreads();
    }
}

// --------------------- split-precision prep kernels ------------------------
__global__ void split_A_kernel(const float* __restrict__ y1,
                               __nv_bfloat16* __restrict__ A3) {
    int idx = blockIdx.x * 256 + threadIdx.x;
    if (idx >= NROW * 128) return;
    int r = idx >> 7, k = idx & 127;            // r = b*256+t
    int bb = r >> 8, t = r & 255;
    float x = y1[(size_t)(t * 16 + bb) * 128 + k];
    __nv_bfloat16 hi = __float2bfloat16(x);
    __nv_bfloat16 lo = __float2bfloat16(x - __bfloat162float(hi));
    A3[(size_t)r * 384 + k]       = hi;
    A3[(size_t)r * 384 + 128 + k] = lo;
    A3[(size_t)r * 384 + 256 + k] = hi;
}

__global__ void split_B_kernel(const float* __restrict__ fc_w,
                               __nv_bfloat16* __restrict__ B3) {
    int idx = blockIdx.x * 256 + threadIdx.x;
    if (idx >= VPAD * 128) return;
    int v = idx >> 7, k = idx & 127;
    float x = (v < VD) ? fc_w[(size_t)v * 128 + k] : 0.0f;
    __nv_bfloat16 hi = __float2bfloat16(x);
    __nv_bfloat16 lo = __float2bfloat16(x - __bfloat162float(hi));
    B3[(size_t)v * 384 + k]       = hi;
    B3[(size_t)v * 384 + 128 + k] = hi;
    B3[(size_t)v * 384 + 256 + k] = lo;
}

// ------------------------------ FC GEMM (mma) ------------------------------
// C[4096, 50048] = A3[4096,384] * B3[50048,384]^T + bias. CTA 128x128,
// 8 warps in 2x4 grid, warp tile 64x32, mma.m16n8k16 bf16->f32.
#define SAST 72    // smem row stride (bf16 elems): 64 + 8 pad

__device__ __forceinline__ void mma16816(float* c, const uint32_t* a,
                                         const uint32_t* b) {
    asm volatile(
        "mma.sync.aligned.m16n8k16.row.col.f32.bf16.bf16.f32 "
        "{%0,%1,%2,%3}, {%4,%5,%6,%7}, {%8,%9}, {%0,%1,%2,%3};"
        : "+f"(c[0]), "+f"(c[1]), "+f"(c[2]), "+f"(c[3])
        : "r"(a[0]), "r"(a[1]), "r"(a[2]), "r"(a[3]), "r"(b[0]), "r"(b[1]));
}

__global__ __launch_bounds__(256, 2) void fc_kernel(
    const __nv_bfloat16* __restrict__ A3, const __nv_bfloat16* __restrict__ B3,
    const float* __restrict__ bias, float* __restrict__ outp)
{
    __shared__ __align__(16) __nv_bfloat16 Asm[128 * SAST];
    __shared__ __align__(16) __nv_bfloat16 Bsm[128 * SAST];

    const int m0 = blockIdx.y * 128;
    const int n0 = blockIdx.x * 128;
    const int tid = threadIdx.x;
    const int lane = tid & 31;
    const int wid = tid >> 5;
    const int wm = wid >> 2, wn = wid & 3;       // 2 x 4 warp grid
    const int grp = lane >> 2, tg = lane & 3;

    float acc[4][4][4] = {};

    for (int kc = 0; kc < 384; kc += 64) {
        // stage A, B k-chunk: 128 rows x 64 cols each, uint4 (8 bf16) loads
        for (int i = tid; i < 1024; i += 256) {
            int r = i >> 3, c8 = i & 7;
            *(uint4*)&Asm[r * SAST + c8 * 8] =
                *(const uint4*)&A3[(size_t)(m0 + r) * 384 + kc + c8 * 8];
            *(uint4*)&Bsm[r * SAST + c8 * 8] =
                *(const uint4*)&B3[(size_t)(n0 + r) * 384 + kc + c8 * 8];
        }
        __syncthreads();

#pragma unroll
        for (int ks = 0; ks < 4; ks++) {
            const int k16 = ks * 16;
            uint32_t a[4][4], bfr[4][2];
#pragma unroll
            for (int mt = 0; mt < 4; mt++) {
                int rl = (wm * 64 + mt * 16 + grp) * SAST + k16 + tg * 2;
                a[mt][0] = *(const uint32_t*)&Asm[rl];
                a[mt][1] = *(const uint32_t*)&Asm[rl + 8 * SAST];
                a[mt][2] = *(const uint32_t*)&Asm[rl + 8];
                a[mt][3] = *(const uint32_t*)&Asm[rl + 8 * SAST + 8];
            }
#pragma unroll
            for (int nt = 0; nt < 4; nt++) {
                int cl = (wn * 32 + nt * 8 + grp) * SAST + k16 + tg * 2;
                bfr[nt][0] = *(const uint32_t*)&Bsm[cl];
                bfr[nt][1] = *(const uint32_t*)&Bsm[cl + 8];
            }
#pragma unroll
            for (int mt = 0; mt < 4; mt++)
#pragma unroll
                for (int nt = 0; nt < 4; nt++)
                    mma16816(acc[mt][nt], a[mt], bfr[nt]);
        }
        __syncthreads();
    }

    // epilogue
#pragma unroll
    for (int mt = 0; mt < 4; mt++) {
#pragma unroll
        for (int nt = 0; nt < 4; nt++) {
            int r0 = m0 + wm * 64 + mt * 16 + grp;
            int c0 = n0 + wn * 32 + nt * 8 + tg * 2;
            float bv0 = 0.f, bv1 = 0.f;
            if (c0 < VD)     bv0 = bias[c0];
            if (c0 + 1 < VD) bv1 = bias[c0 + 1];
            if (c0 < VD)
                outp[(size_t)r0 * VD + c0] = acc[mt][nt][0] + bv0;
            if (c0 + 1 < VD)
                outp[(size_t)r0 * VD + c0 + 1] = acc[mt][nt][1] + bv1;
            if (c0 < VD)
                outp[(size_t)(r0 + 8) * VD + c0] = acc[mt][nt][2] + bv0;
            if (c0 + 1 < VD)
                outp[(size_t)(r0 + 8) * VD + c0 + 1] = acc[mt][nt][3] + bv1;
        }
    }
}

// ------------------------------- launch ------------------------------------
extern "C" void kernel_launch(void* const* d_in, const int* in_sizes, int n_in,
                              void* d_out, int out_size) {
    const int*   x     = (const int*)d_in[0];
    const float* emb   = (const float*)d_in[1];
    const float* W_ih0 = (const float*)d_in[2];
    const float* W_hh0 = (const float*)d_in[3];
    const float* b_ih0 = (const float*)d_in[4];
    const float* b_hh0 = (const float*)d_in[5];
    const float* W_ih1 = (const float*)d_in[6];
    const float* W_hh1 = (const float*)d_in[7];
    const float* b_ih1 = (const float*)d_in[8];
    const float* b_hh1 = (const float*)d_in[9];
    const float* fc_w  = (const float*)d_in[10];
    const float* fc_b  = (const float*)d_in[11];
    float* outp = (float*)d_out;

    float* xp0; cudaGetSymbolAddress((void**)&xp0, g_xp0);
    float* xp1; cudaGetSymbolAddress((void**)&xp1, g_xp1);
    float* y0;  cudaGetSymbolAddress((void**)&y0,  g_y0);
    float* y1;  cudaGetSymbolAddress((void**)&y1,  g_y1);
    __nv_bfloat16* A3; cudaGetSymbolAddress((void**)&A3, g_A3);
    __nv_bfloat16* B3; cudaGetSymbolAddress((void**)&B3, g_B3);
    int* f0; cudaGetSymbolAddress((void**)&f0, g_flags0);
    int* f1; cudaGetSymbolAddress((void**)&f1, g_flags1);

    zero_flags_kernel<<<32, 256>>>();
    split_B_kernel<<<(VPAD * 128 + 255) / 256, 256>>>(fc_w, B3);

    dim3 pgrid(GDIM / 64, NROW / 64);
    proj_kernel<<<pgrid, 256>>>(nullptr, x, emb, W_ih0, b_ih0, b_hh0, xp0);
    lstm_kernel<<<32, 256>>>(xp0, W_hh0, y0, f0, outp, 0);
    proj_kernel<<<pgrid, 256>>>(y0, nullptr, emb, W_ih1, b_ih1, b_hh1, xp1);
    lstm_kernel<<<32, 256>>>(xp1, W_hh1, y1, f1, outp, 1);

    split_A_kernel<<<(NROW * 128 + 255) / 256, 256>>>(y1, A3);
    dim3 fgrid(VPAD / 128, NROW / 128);
    fc_kernel<<<fgrid, 256>>>(A3, B3, fc_b, outp);
}

// round 12
// speedup vs baseline: 1.2929x; 1.2929x over previous
#include <cuda_runtime.h>
#include <cuda_bf16.h>
#include <stdint.h>

#define BD 16
#define TD 256
#define HD 128
#define VD 50000
#define VPAD 50048
#define NROW 4096              // B*T
#define GDIM 512               // 4*H
#define HOFF 204800000l        // start of h in out (16*256*50000)
#define COFF 204804096l        // start of c in out

// ------------------------- scratch (device globals) ------------------------
__device__ float g_xp0[NROW * GDIM];
__device__ float g_xp1[NROW * GDIM];
__device__ float g_y0[NROW * HD];
__device__ float g_y1[NROW * HD];
__device__ __nv_bfloat16 g_A3[NROW * 384];   // [b*256+t][384] (hi|lo|hi)
__device__ __nv_bfloat16 g_B3[VPAD * 384];   // [v][384]       (hi|hi|lo)

// ---------------- projection GEMM: out[r][g] = A[r] . W[g] + b1[g]+b2[g] ----
// A row r (= t*16+b) is emb[x[b][t]] when xids != 0, else Arows + r*128.
__global__ __launch_bounds__(256) void proj_kernel(
    const float* __restrict__ Arows, const int* __restrict__ xids,
    const float* __restrict__ emb, const float* __restrict__ W,
    const float* __restrict__ b1, const float* __restrict__ b2,
    float* __restrict__ outp)
{
    __shared__ float Asm[64][65];   // [k][m]
    __shared__ float Bsm[64][65];   // [k][g]
    const int tb0 = blockIdx.y * 64;
    const int g0  = blockIdx.x * 64;
    const int tid = threadIdx.x;
    const int tx = tid & 15, ty = tid >> 4;
    float acc[4][4] = {};

    for (int kc = 0; kc < 128; kc += 64) {
        for (int i = tid; i < 64 * 64; i += 256) {
            int m = i >> 6, k = i & 63;
            int r = tb0 + m;
            const float* ar;
            if (xids) ar = emb + (size_t)xids[(r & 15) * 256 + (r >> 4)] * 128;
            else      ar = Arows + (size_t)r * 128;
            Asm[k][m] = ar[kc + k];
        }
        for (int i = tid; i < 64 * 64; i += 256) {
            int n = i >> 6, k = i & 63;
            Bsm[k][n] = W[(size_t)(g0 + n) * 128 + kc + k];
        }
        __syncthreads();
#pragma unroll 16
        for (int k = 0; k < 64; k++) {
            float a[4], bb[4];
#pragma unroll
            for (int i = 0; i < 4; i++) a[i] = Asm[k][ty * 4 + i];
#pragma unroll
            for (int j = 0; j < 4; j++) bb[j] = Bsm[k][tx * 4 + j];
#pragma unroll
            for (int i = 0; i < 4; i++)
#pragma unroll
                for (int j = 0; j < 4; j++) acc[i][j] += a[i] * bb[j];
        }
        __syncthreads();
    }
#pragma unroll
    for (int i = 0; i < 4; i++) {
        int r = tb0 + ty * 4 + i;
#pragma unroll
        for (int j = 0; j < 4; j++) {
            int g = g0 + tx * 4 + j;
            outp[(size_t)r * GDIM + g] = acc[i][j] + b1[g] + b2[g];
        }
    }
}

// --------------------------- LSTM layer (cluster) --------------------------
// 32 CTAs in clusters of 2: b = blk>>1, half = rank = blk&1. 256 threads.
// Thread owns one W_hh gate row (gate*128 + half*64 + u) register-resident as
// 64 packed f32x2. h state double-buffered in smem; halves exchanged via
// st.shared::cluster (DSMEM) + one barrier.cluster per step.
__device__ __forceinline__ float sigmoidf_(float x) {
    return 1.0f / (1.0f + __expf(-x));
}
__device__ __forceinline__ void fma2_(unsigned long long& acc,
                                      unsigned long long a,
                                      unsigned long long b) {
    asm("fma.rn.f32x2 %0, %1, %2, %0;" : "+l"(acc) : "l"(a), "l"(b));
}
__device__ __forceinline__ float2 unpk_(unsigned long long v) {
    float2 r;
    asm("mov.b64 {%0, %1}, %2;" : "=f"(r.x), "=f"(r.y) : "l"(v));
    return r;
}

__global__ __launch_bounds__(256, 1) __cluster_dims__(2, 1, 1)
void lstm_kernel(const float* __restrict__ xp, const float* __restrict__ Whh,
                 float* __restrict__ y, float* __restrict__ outp, int layer)
{
    const int b = blockIdx.x >> 1;
    const int half = blockIdx.x & 1;      // == cluster rank
    const int tid = threadIdx.x;
    const int u = tid & 63, gate = tid >> 6;
    const int row = gate * 128 + half * 64 + u;

    __shared__ __align__(16) float h_sm[2][128];   // double-buffered h state
    __shared__ float gates_sm[256];

    // W_hh row, packed as 64 f32x2 in registers
    unsigned long long wq[64];
    {
        const unsigned long long* wrow =
            reinterpret_cast<const unsigned long long*>(Whh) + (size_t)row * 64;
#pragma unroll
        for (int k = 0; k < 64; k++) wq[k] = wrow[k];
    }

    if (tid < 128) { h_sm[0][tid] = 0.0f; h_sm[1][tid] = 0.0f; }
    float c = 0.0f;
    __syncthreads();

    for (int t = 0; t < TD; t++) {
        const int p = t & 1;
        const size_t rbase = (size_t)(t * 16 + b);
        float xv = xp[rbase * GDIM + row];          // prefetch

        unsigned long long a0 = 0ull, a1 = 0ull, a2 = 0ull, a3 = 0ull;
        const ulonglong2* h2 = (const ulonglong2*)h_sm[p];
#pragma unroll
        for (int k = 0; k < 16; k++) {
            ulonglong2 hv0 = h2[2 * k];
            ulonglong2 hv1 = h2[2 * k + 1];
            fma2_(a0, wq[4 * k + 0], hv0.x);
            fma2_(a1, wq[4 * k + 1], hv0.y);
            fma2_(a2, wq[4 * k + 2], hv1.x);
            fma2_(a3, wq[4 * k + 3], hv1.y);
        }
        float2 f0 = unpk_(a0), f1 = unpk_(a1), f2 = unpk_(a2), f3 = unpk_(a3);
        gates_sm[tid] = xv + ((f0.x + f0.y) + (f1.x + f1.y)) +
                             ((f2.x + f2.y) + (f3.x + f3.y));
        __syncthreads();

        if (tid < 64) {
            float i_ = sigmoidf_(gates_sm[tid]);
            float f_ = sigmoidf_(gates_sm[64 + tid]);
            float g_ = tanhf(gates_sm[128 + tid]);
            float o_ = sigmoidf_(gates_sm[192 + tid]);
            c = f_ * c + i_ * g_;
            float h = o_ * tanhf(c);
            int gu = half * 64 + tid;
            h_sm[p ^ 1][gu] = h;                    // own buffer
            // peer CTA's buffer via DSMEM
            uint32_t laddr;
            asm("{ .reg .u64 t0; cvta.to.shared.u64 t0, %1; cvt.u32.u64 %0, t0; }"
                : "=r"(laddr) : "l"(&h_sm[p ^ 1][gu]));
            uint32_t raddr;
            asm("mapa.shared::cluster.u32 %0, %1, %2;"
                : "=r"(raddr) : "r"(laddr), "r"(half ^ 1));
            asm volatile("st.shared::cluster.f32 [%0], %1;"
                         :: "r"(raddr), "f"(h) : "memory");
            __stcg(&y[rbase * HD + gu], h);
            if (t == TD - 1) {
                outp[HOFF + (size_t)layer * 2048 + b * 128 + gu] = h;
                outp[COFF + (size_t)layer * 2048 + b * 128 + gu] = c;
            }
        }
        // release own writes, acquire peer's (subsumes __syncthreads)
        asm volatile("barrier.cluster.arrive.aligned;" ::: "memory");
        asm volatile("barrier.cluster.wait.aligned;" ::: "memory");
    }
}

// --------------------- split-precision prep kernels ------------------------
__global__ void split_A_kernel(const float* __restrict__ y1,
                               __nv_bfloat16* __restrict__ A3) {
    int idx = blockIdx.x * 256 + threadIdx.x;
    if (idx >= NROW * 128) return;
    int r = idx >> 7, k = idx & 127;            // r = b*256+t
    int bb = r >> 8, t = r & 255;
    float x = y1[(size_t)(t * 16 + bb) * 128 + k];
    __nv_bfloat16 hi = __float2bfloat16(x);
    __nv_bfloat16 lo = __float2bfloat16(x - __bfloat162float(hi));
    A3[(size_t)r * 384 + k]       = hi;
    A3[(size_t)r * 384 + 128 + k] = lo;
    A3[(size_t)r * 384 + 256 + k] = hi;
}

__global__ void split_B_kernel(const float* __restrict__ fc_w,
                               __nv_bfloat16* __restrict__ B3) {
    int idx = blockIdx.x * 256 + threadIdx.x;
    if (idx >= VPAD * 128) return;
    int v = idx >> 7, k = idx & 127;
    float x = (v < VD) ? fc_w[(size_t)v * 128 + k] : 0.0f;
    __nv_bfloat16 hi = __float2bfloat16(x);
    __nv_bfloat16 lo = __float2bfloat16(x - __bfloat162float(hi));
    B3[(size_t)v * 384 + k]       = hi;
    B3[(size_t)v * 384 + 128 + k] = hi;
    B3[(size_t)v * 384 + 256 + k] = lo;
}

// ------------------------------ FC GEMM (mma) ------------------------------
// C[4096, 50048] = A3[4096,384] * B3[50048,384]^T + bias. CTA 128x128,
// 8 warps in 2x4 grid, warp tile 64x32, mma.m16n8k16 bf16->f32.
#define SAST 72    // smem row stride (bf16 elems): 64 + 8 pad

__device__ __forceinline__ void mma16816(float* c, const uint32_t* a,
                                         const uint32_t* b) {
    asm volatile(
        "mma.sync.aligned.m16n8k16.row.col.f32.bf16.bf16.f32 "
        "{%0,%1,%2,%3}, {%4,%5,%6,%7}, {%8,%9}, {%0,%1,%2,%3};"
        : "+f"(c[0]), "+f"(c[1]), "+f"(c[2]), "+f"(c[3])
        : "r"(a[0]), "r"(a[1]), "r"(a[2]), "r"(a[3]), "r"(b[0]), "r"(b[1]));
}

__global__ __launch_bounds__(256, 2) void fc_kernel(
    const __nv_bfloat16* __restrict__ A3, const __nv_bfloat16* __restrict__ B3,
    const float* __restrict__ bias, float* __restrict__ outp)
{
    __shared__ __align__(16) __nv_bfloat16 Asm[128 * SAST];
    __shared__ __align__(16) __nv_bfloat16 Bsm[128 * SAST];

    const int m0 = blockIdx.y * 128;
    const int n0 = blockIdx.x * 128;
    const int tid = threadIdx.x;
    const int lane = tid & 31;
    const int wid = tid >> 5;
    const int wm = wid >> 2, wn = wid & 3;       // 2 x 4 warp grid
    const int grp = lane >> 2, tg = lane & 3;

    float acc[4][4][4] = {};

    for (int kc = 0; kc < 384; kc += 64) {
        for (int i = tid; i < 1024; i += 256) {
            int r = i >> 3, c8 = i & 7;
            *(uint4*)&Asm[r * SAST + c8 * 8] =
                *(const uint4*)&A3[(size_t)(m0 + r) * 384 + kc + c8 * 8];
            *(uint4*)&Bsm[r * SAST + c8 * 8] =
                *(const uint4*)&B3[(size_t)(n0 + r) * 384 + kc + c8 * 8];
        }
        __syncthreads();

#pragma unroll
        for (int ks = 0; ks < 4; ks++) {
            const int k16 = ks * 16;
            uint32_t a[4][4], bfr[4][2];
#pragma unroll
            for (int mt = 0; mt < 4; mt++) {
                int rl = (wm * 64 + mt * 16 + grp) * SAST + k16 + tg * 2;
                a[mt][0] = *(const uint32_t*)&Asm[rl];
                a[mt][1] = *(const uint32_t*)&Asm[rl + 8 * SAST];
                a[mt][2] = *(const uint32_t*)&Asm[rl + 8];
                a[mt][3] = *(const uint32_t*)&Asm[rl + 8 * SAST + 8];
            }
#pragma unroll
            for (int nt = 0; nt < 4; nt++) {
                int cl = (wn * 32 + nt * 8 + grp) * SAST + k16 + tg * 2;
                bfr[nt][0] = *(const uint32_t*)&Bsm[cl];
                bfr[nt][1] = *(const uint32_t*)&Bsm[cl + 8];
            }
#pragma unroll
            for (int mt = 0; mt < 4; mt++)
#pragma unroll
                for (int nt = 0; nt < 4; nt++)
                    mma16816(acc[mt][nt], a[mt], bfr[nt]);
        }
        __syncthreads();
    }

#pragma unroll
    for (int mt = 0; mt < 4; mt++) {
#pragma unroll
        for (int nt = 0; nt < 4; nt++) {
            int r0 = m0 + wm * 64 + mt * 16 + grp;
            int c0 = n0 + wn * 32 + nt * 8 + tg * 2;
            float bv0 = 0.f, bv1 = 0.f;
            if (c0 < VD)     bv0 = bias[c0];
            if (c0 + 1 < VD) bv1 = bias[c0 + 1];
            if (c0 < VD)
                outp[(size_t)r0 * VD + c0] = acc[mt][nt][0] + bv0;
            if (c0 + 1 < VD)
                outp[(size_t)r0 * VD + c0 + 1] = acc[mt][nt][1] + bv1;
            if (c0 < VD)
                outp[(size_t)(r0 + 8) * VD + c0] = acc[mt][nt][2] + bv0;
            if (c0 + 1 < VD)
                outp[(size_t)(r0 + 8) * VD + c0 + 1] = acc[mt][nt][3] + bv1;
        }
    }
}

// ------------------------------- launch ------------------------------------
extern "C" void kernel_launch(void* const* d_in, const int* in_sizes, int n_in,
                              void* d_out, int out_size) {
    const int*   x     = (const int*)d_in[0];
    const float* emb   = (const float*)d_in[1];
    const float* W_ih0 = (const float*)d_in[2];
    const float* W_hh0 = (const float*)d_in[3];
    const float* b_ih0 = (const float*)d_in[4];
    const float* b_hh0 = (const float*)d_in[5];
    const float* W_ih1 = (const float*)d_in[6];
    const float* W_hh1 = (const float*)d_in[7];
    const float* b_ih1 = (const float*)d_in[8];
    const float* b_hh1 = (const float*)d_in[9];
    const float* fc_w  = (const float*)d_in[10];
    const float* fc_b  = (const float*)d_in[11];
    float* outp = (float*)d_out;

    float* xp0; cudaGetSymbolAddress((void**)&xp0, g_xp0);
    float* xp1; cudaGetSymbolAddress((void**)&xp1, g_xp1);
    float* y0;  cudaGetSymbolAddress((void**)&y0,  g_y0);
    float* y1;  cudaGetSymbolAddress((void**)&y1,  g_y1);
    __nv_bfloat16* A3; cudaGetSymbolAddress((void**)&A3, g_A3);
    __nv_bfloat16* B3; cudaGetSymbolAddress((void**)&B3, g_B3);

    split_B_kernel<<<(VPAD * 128 + 255) / 256, 256>>>(fc_w, B3);

    dim3 pgrid(GDIM / 64, NROW / 64);
    proj_kernel<<<pgrid, 256>>>(nullptr, x, emb, W_ih0, b_ih0, b_hh0, xp0);
    lstm_kernel<<<32, 256>>>(xp0, W_hh0, y0, outp, 0);
    proj_kernel<<<pgrid, 256>>>(y0, nullptr, emb, W_ih1, b_ih1, b_hh1, xp1);
    lstm_kernel<<<32, 256>>>(xp1, W_hh1, y1, outp, 1);

    split_A_kernel<<<(NROW * 128 + 255) / 256, 256>>>(y1, A3);
    dim3 fgrid(VPAD / 128, NROW / 128);
    fc_kernel<<<fgrid, 256>>>(A3, B3, fc_b, outp);
}

// round 15
// speedup vs baseline: 1.5662x; 1.2114x over previous
#include <cuda_runtime.h>
#include <cuda_bf16.h>
#include <stdint.h>

#define BD 16
#define TD 256
#define HD 128
#define VD 50000
#define VPAD 50048
#define NROW 4096              // B*T
#define GDIM 512               // 4*H
#define HOFF 204800000l        // start of h in out (16*256*50000)
#define COFF 204804096l        // start of c in out

// ------------------------- scratch (device globals) ------------------------
__device__ float g_xp0[NROW * GDIM];
__device__ float g_xp1[NROW * GDIM];
__device__ float g_y0[NROW * HD];
__device__ float g_y1[NROW * HD];
__device__ __nv_bfloat16 g_A3[NROW * 384];   // [b*256+t][384] (hi|lo|hi)
__device__ __nv_bfloat16 g_B3[VPAD * 384];   // [v][384]       (hi|hi|lo)

__device__ __forceinline__ uint32_t smem_u32(const void* p) {
    return (uint32_t)__cvta_generic_to_shared(p);
}

// ---------------- projection GEMM: out[r][g] = A[r] . W[g] + b1[g]+b2[g] ----
__global__ __launch_bounds__(256) void proj_kernel(
    const float* __restrict__ Arows, const int* __restrict__ xids,
    const float* __restrict__ emb, const float* __restrict__ W,
    const float* __restrict__ b1, const float* __restrict__ b2,
    float* __restrict__ outp)
{
    __shared__ float Asm[64][65];   // [k][m]
    __shared__ float Bsm[64][65];   // [k][g]
    const int tb0 = blockIdx.y * 64;
    const int g0  = blockIdx.x * 64;
    const int tid = threadIdx.x;
    const int tx = tid & 15, ty = tid >> 4;
    float acc[4][4] = {};

    for (int kc = 0; kc < 128; kc += 64) {
        for (int i = tid; i < 64 * 64; i += 256) {
            int m = i >> 6, k = i & 63;
            int r = tb0 + m;
            const float* ar;
            if (xids) ar = emb + (size_t)xids[(r & 15) * 256 + (r >> 4)] * 128;
            else      ar = Arows + (size_t)r * 128;
            Asm[k][m] = ar[kc + k];
        }
        for (int i = tid; i < 64 * 64; i += 256) {
            int n = i >> 6, k = i & 63;
            Bsm[k][n] = W[(size_t)(g0 + n) * 128 + kc + k];
        }
        __syncthreads();
#pragma unroll 16
        for (int k = 0; k < 64; k++) {
            float a[4], bb[4];
#pragma unroll
            for (int i = 0; i < 4; i++) a[i] = Asm[k][ty * 4 + i];
#pragma unroll
            for (int j = 0; j < 4; j++) bb[j] = Bsm[k][tx * 4 + j];
#pragma unroll
            for (int i = 0; i < 4; i++)
#pragma unroll
                for (int j = 0; j < 4; j++) acc[i][j] += a[i] * bb[j];
        }
        __syncthreads();
    }
#pragma unroll
    for (int i = 0; i < 4; i++) {
        int r = tb0 + ty * 4 + i;
#pragma unroll
        for (int j = 0; j < 4; j++) {
            int g = g0 + tx * 4 + j;
            outp[(size_t)r * GDIM + g] = acc[i][j] + b1[g] + b2[g];
        }
    }
}

// --------------------------- LSTM layer (cluster) --------------------------
// Blocks 0..31: clusters of 2 (b = blk>>1, half = rank = blk&1), 256 threads.
// Thread owns one W_hh gate row register-resident as 64 packed f32x2.
// h double-buffered in smem; halves exchanged via st.shared::cluster + an
// mbarrier parity handshake (release/acquire at cluster scope).
// Blocks >= 32 (layer-0 launch only): do split_B work on idle SMs.
__device__ __forceinline__ float fast_sig(float x) {
    return __fdividef(1.0f, 1.0f + __expf(-x));
}
__device__ __forceinline__ float fast_tanh(float x) {
    float e = __expf(2.0f * x);
    return 1.0f - __fdividef(2.0f, e + 1.0f);
}
__device__ __forceinline__ void fma2_(unsigned long long& acc,
                                      unsigned long long a,
                                      unsigned long long b) {
    asm("fma.rn.f32x2 %0, %1, %2, %0;" : "+l"(acc) : "l"(a), "l"(b));
}
__device__ __forceinline__ float2 unpk_(unsigned long long v) {
    float2 r;
    asm("mov.b64 {%0, %1}, %2;" : "=f"(r.x), "=f"(r.y) : "l"(v));
    return r;
}
#define MBAR_WAIT_CL(addr, par) \
    asm volatile("{\n\t.reg .pred P1;\n\tWAITL_%=:\n\t" \
        "mbarrier.try_wait.parity.acquire.cluster.shared::cta.b64 P1, [%0], %1;\n\t" \
        "@!P1 bra WAITL_%=;\n\t}" :: "r"(addr), "r"(par) : "memory")

__global__ __launch_bounds__(256, 1) __cluster_dims__(2, 1, 1)
void lstm_kernel(const float* __restrict__ xp, const float* __restrict__ Whh,
                 float* __restrict__ y, float* __restrict__ outp, int layer,
                 const float* __restrict__ fc_w, __nv_bfloat16* __restrict__ B3)
{
    if (blockIdx.x >= 32) {
        // ---- fused split_B (layer-0 launch only; extra blocks) ----
        int nb = gridDim.x - 32;
        for (int idx = (blockIdx.x - 32) * 256 + threadIdx.x;
             idx < VPAD * 128; idx += nb * 256) {
            int v = idx >> 7, k = idx & 127;
            float xw = (v < VD) ? fc_w[(size_t)v * 128 + k] : 0.0f;
            __nv_bfloat16 hi = __float2bfloat16(xw);
            __nv_bfloat16 lo = __float2bfloat16(xw - __bfloat162float(hi));
            B3[(size_t)v * 384 + k]       = hi;
            B3[(size_t)v * 384 + 128 + k] = hi;
            B3[(size_t)v * 384 + 256 + k] = lo;
        }
        return;
    }

    const int b = blockIdx.x >> 1;
    const int half = blockIdx.x & 1;      // == cluster rank
    const int tid = threadIdx.x;
    const int u = tid & 63, gate = tid >> 6;
    const int row = gate * 128 + half * 64 + u;

    __shared__ __align__(16) float h_sm[2][128];
    __shared__ float gates_sm[256];
    __shared__ __align__(8) unsigned long long mbar_sm[2];

    // W_hh row packed as 64 f32x2
    unsigned long long wq[64];
    {
        const unsigned long long* wrow =
            reinterpret_cast<const unsigned long long*>(Whh) + (size_t)row * 64;
#pragma unroll
        for (int k = 0; k < 64; k++) wq[k] = wrow[k];
    }

    if (tid < 128) { h_sm[0][tid] = 0.0f; h_sm[1][tid] = 0.0f; }
    if (tid == 0) {
        asm volatile("mbarrier.init.shared.b64 [%0], %1;"
                     :: "r"(smem_u32(&mbar_sm[0])), "r"(64) : "memory");
        asm volatile("mbarrier.init.shared.b64 [%0], %1;"
                     :: "r"(smem_u32(&mbar_sm[1])), "r"(64) : "memory");
    }
    float c = 0.0f;
    __syncthreads();
    // peer's mbarriers must be initialized before our first remote arrive
    asm volatile("barrier.cluster.arrive.aligned;" ::: "memory");
    asm volatile("barrier.cluster.wait.aligned;" ::: "memory");

    // remote (peer) addresses
    const int peer = half ^ 1;
    uint32_t lm0 = smem_u32(&mbar_sm[0]), lm1 = smem_u32(&mbar_sm[1]);
    uint32_t lh0 = smem_u32(&h_sm[0][0]), lh1 = smem_u32(&h_sm[1][0]);
    uint32_t rm0, rm1, rh0, rh1;
    asm("mapa.shared::cluster.u32 %0, %1, %2;" : "=r"(rm0) : "r"(lm0), "r"(peer));
    asm("mapa.shared::cluster.u32 %0, %1, %2;" : "=r"(rm1) : "r"(lm1), "r"(peer));
    asm("mapa.shared::cluster.u32 %0, %1, %2;" : "=r"(rh0) : "r"(lh0), "r"(peer));
    asm("mapa.shared::cluster.u32 %0, %1, %2;" : "=r"(rh1) : "r"(lh1), "r"(peer));

    float xv = xp[(size_t)b * GDIM + row];         // t=0 prefetch

    for (int t = 0; t < TD; t++) {
        const int p = t & 1;
        const size_t rbase = (size_t)(t * 16 + b);

        unsigned long long a0 = 0ull, a1 = 0ull, a2 = 0ull, a3 = 0ull;
        const ulonglong2* h2 = (const ulonglong2*)h_sm[p];
#pragma unroll
        for (int k = 0; k < 16; k++) {
            ulonglong2 hv0 = h2[2 * k];
            ulonglong2 hv1 = h2[2 * k + 1];
            fma2_(a0, wq[4 * k + 0], hv0.x);
            fma2_(a1, wq[4 * k + 1], hv0.y);
            fma2_(a2, wq[4 * k + 2], hv1.x);
            fma2_(a3, wq[4 * k + 3], hv1.y);
        }
        float2 f0 = unpk_(a0), f1 = unpk_(a1), f2 = unpk_(a2), f3 = unpk_(a3);
        float gval = xv + ((f0.x + f0.y) + (f1.x + f1.y)) +
                          ((f2.x + f2.y) + (f3.x + f3.y));
        if (t + 1 < TD)                            // prefetch next x-projection
            xv = xp[(size_t)((t + 1) * 16 + b) * GDIM + row];
        gates_sm[tid] = gval;
        __syncthreads();

        if (tid < 64) {
            float i_ = fast_sig(gates_sm[tid]);
            float f_ = fast_sig(gates_sm[64 + tid]);
            float g_ = fast_tanh(gates_sm[128 + tid]);
            float o_ = fast_sig(gates_sm[192 + tid]);
            c = f_ * c + i_ * g_;
            float h = o_ * fast_tanh(c);
            int gu = half * 64 + tid;
            h_sm[p ^ 1][gu] = h;                   // own buffer
            __stcg(&y[rbase * HD + gu], h);
            if (t < TD - 1) {
                uint32_t rha = (p ? rh0 : rh1) + 4u * (uint32_t)gu;
                asm volatile("st.shared::cluster.f32 [%0], %1;"
                             :: "r"(rha), "f"(h) : "memory");
                uint32_t rma = (p ? rm0 : rm1);
                asm volatile(
                    "mbarrier.arrive.release.cluster.shared::cluster.b64 _, [%0];"
                    :: "r"(rma) : "memory");
            } else {
                outp[HOFF + (size_t)layer * 2048 + b * 128 + gu] = h;
                outp[COFF + (size_t)layer * 2048 + b * 128 + gu] = c;
            }
        }
        if (t < TD - 1) {
            uint32_t lma = (p ? lm0 : lm1);        // local mbar[p^1]
            MBAR_WAIT_CL(lma, (t >> 1) & 1);
        }
        __syncthreads();
    }
}

// --------------------- split-precision prep (A only) -----------------------
__global__ void split_A_kernel(const float* __restrict__ y1,
                               __nv_bfloat16* __restrict__ A3) {
    int idx = blockIdx.x * 256 + threadIdx.x;
    if (idx >= NROW * 128) return;
    int r = idx >> 7, k = idx & 127;            // r = b*256+t
    int bb = r >> 8, t = r & 255;
    float x = y1[(size_t)(t * 16 + bb) * 128 + k];
    __nv_bfloat16 hi = __float2bfloat16(x);
    __nv_bfloat16 lo = __float2bfloat16(x - __bfloat162float(hi));
    A3[(size_t)r * 384 + k]       = hi;
    A3[(size_t)r * 384 + 128 + k] = lo;
    A3[(size_t)r * 384 + 256 + k] = hi;
}

// ------------------------------ FC GEMM (mma) ------------------------------
// C[4096, 50048] = A3[4096,384] * B3[50048,384]^T + bias. CTA 128x128,
// 8 warps 2x4, warp tile 64x32, mma.m16n8k16 bf16->f32, 3-stage cp.async.
#define SAST 72                      // smem row stride (64 + 8 pad) bf16
#define STAGE_ELEMS (128 * SAST)     // per array per stage
#define FC_DSMEM (3 * 2 * STAGE_ELEMS * 2)   // 110592 bytes

__device__ __forceinline__ void cpasync16(void* smem, const void* gmem) {
    asm volatile("cp.async.cg.shared.global [%0], [%1], 16;"
                 :: "r"(smem_u32(smem)), "l"(gmem));
}
__device__ __forceinline__ void mma16816(float* c, const uint32_t* a,
                                         const uint32_t* b) {
    asm volatile(
        "mma.sync.aligned.m16n8k16.row.col.f32.bf16.bf16.f32 "
        "{%0,%1,%2,%3}, {%4,%5,%6,%7}, {%8,%9}, {%0,%1,%2,%3};"
        : "+f"(c[0]), "+f"(c[1]), "+f"(c[2]), "+f"(c[3])
        : "r"(a[0]), "r"(a[1]), "r"(a[2]), "r"(a[3]), "r"(b[0]), "r"(b[1]));
}

__global__ __launch_bounds__(256, 2) void fc_kernel(
    const __nv_bfloat16* __restrict__ A3, const __nv_bfloat16* __restrict__ B3,
    const float* __restrict__ bias, float* __restrict__ outp)
{
    extern __shared__ __align__(16) __nv_bfloat16 fcsm[];

    const int m0 = blockIdx.y * 128;
    const int n0 = blockIdx.x * 128;
    const int tid = threadIdx.x;
    const int lane = tid & 31;
    const int wid = tid >> 5;
    const int wm = wid >> 2, wn = wid & 3;       // 2 x 4 warp grid
    const int grp = lane >> 2, tg = lane & 3;

    auto load_stage = [&](int st, int kc) {
        __nv_bfloat16* As = fcsm + st * (2 * STAGE_ELEMS);
        __nv_bfloat16* Bs = As + STAGE_ELEMS;
        for (int i = tid; i < 1024; i += 256) {
            int r = i >> 3, c8 = i & 7;
            cpasync16(&As[r * SAST + c8 * 8],
                      &A3[(size_t)(m0 + r) * 384 + kc + c8 * 8]);
            cpasync16(&Bs[r * SAST + c8 * 8],
                      &B3[(size_t)(n0 + r) * 384 + kc + c8 * 8]);
        }
        asm volatile("cp.async.commit_group;" ::: "memory");
    };

    load_stage(0, 0);
    load_stage(1, 64);

    float acc[4][4][4] = {};

    for (int ch = 0; ch < 6; ch++) {
        if (ch < 4) asm volatile("cp.async.wait_group 1;" ::: "memory");
        else        asm volatile("cp.async.wait_group 0;" ::: "memory");
        __syncthreads();
        if (ch + 2 < 6) load_stage((ch + 2) % 3, (ch + 2) * 64);

        const __nv_bfloat16* As = fcsm + (ch % 3) * (2 * STAGE_ELEMS);
        const __nv_bfloat16* Bs = As + STAGE_ELEMS;
#pragma unroll
        for (int ks = 0; ks < 4; ks++) {
            const int k16 = ks * 16;
            uint32_t a[4][4], bfr[4][2];
#pragma unroll
            for (int mt = 0; mt < 4; mt++) {
                int rl = (wm * 64 + mt * 16 + grp) * SAST + k16 + tg * 2;
                a[mt][0] = *(const uint32_t*)&As[rl];
                a[mt][1] = *(const uint32_t*)&As[rl + 8 * SAST];
                a[mt][2] = *(const uint32_t*)&As[rl + 8];
                a[mt][3] = *(const uint32_t*)&As[rl + 8 * SAST + 8];
            }
#pragma unroll
            for (int nt = 0; nt < 4; nt++) {
                int cl = (wn * 32 + nt * 8 + grp) * SAST + k16 + tg * 2;
                bfr[nt][0] = *(const uint32_t*)&Bs[cl];
                bfr[nt][1] = *(const uint32_t*)&Bs[cl + 8];
            }
#pragma unroll
            for (int mt = 0; mt < 4; mt++)
#pragma unroll
                for (int nt = 0; nt < 4; nt++)
                    mma16816(acc[mt][nt], a[mt], bfr[nt]);
        }
    }

#pragma unroll
    for (int mt = 0; mt < 4; mt++) {
#pragma unroll
        for (int nt = 0; nt < 4; nt++) {
            int r0 = m0 + wm * 64 + mt * 16 + grp;
            int c0 = n0 + wn * 32 + nt * 8 + tg * 2;
            float bv0 = 0.f, bv1 = 0.f;
            if (c0 < VD)     bv0 = bias[c0];
            if (c0 + 1 < VD) bv1 = bias[c0 + 1];
            if (c0 < VD)
                outp[(size_t)r0 * VD + c0] = acc[mt][nt][0] + bv0;
            if (c0 + 1 < VD)
                outp[(size_t)r0 * VD + c0 + 1] = acc[mt][nt][1] + bv1;
            if (c0 < VD)
                outp[(size_t)(r0 + 8) * VD + c0] = acc[mt][nt][2] + bv0;
            if (c0 + 1 < VD)
                outp[(size_t)(r0 + 8) * VD + c0 + 1] = acc[mt][nt][3] + bv1;
        }
    }
}

// ------------------------------- launch ------------------------------------
extern "C" void kernel_launch(void* const* d_in, const int* in_sizes, int n_in,
                              void* d_out, int out_size) {
    const int*   x     = (const int*)d_in[0];
    const float* emb   = (const float*)d_in[1];
    const float* W_ih0 = (const float*)d_in[2];
    const float* W_hh0 = (const float*)d_in[3];
    const float* b_ih0 = (const float*)d_in[4];
    const float* b_hh0 = (const float*)d_in[5];
    const float* W_ih1 = (const float*)d_in[6];
    const float* W_hh1 = (const float*)d_in[7];
    const float* b_ih1 = (const float*)d_in[8];
    const float* b_hh1 = (const float*)d_in[9];
    const float* fc_w  = (const float*)d_in[10];
    const float* fc_b  = (const float*)d_in[11];
    float* outp = (float*)d_out;

    float* xp0; cudaGetSymbolAddress((void**)&xp0, g_xp0);
    float* xp1; cudaGetSymbolAddress((void**)&xp1, g_xp1);
    float* y0;  cudaGetSymbolAddress((void**)&y0,  g_y0);
    float* y1;  cudaGetSymbolAddress((void**)&y1,  g_y1);
    __nv_bfloat16* A3; cudaGetSymbolAddress((void**)&A3, g_A3);
    __nv_bfloat16* B3; cudaGetSymbolAddress((void**)&B3, g_B3);

    cudaFuncSetAttribute(fc_kernel,
                         cudaFuncAttributeMaxDynamicSharedMemorySize, FC_DSMEM);

    dim3 pgrid(GDIM / 64, NROW / 64);
    proj_kernel<<<pgrid, 256>>>(nullptr, x, emb, W_ih0, b_ih0, b_hh0, xp0);
    // layer-0 LSTM + fused split_B on extra blocks
    lstm_kernel<<<256, 256>>>(xp0, W_hh0, y0, outp, 0, fc_w, B3);
    proj_kernel<<<pgrid, 256>>>(y0, nullptr, emb, W_ih1, b_ih1, b_hh1, xp1);
    lstm_kernel<<<32, 256>>>(xp1, W_hh1, y1, outp, 1, fc_w, B3);

    split_A_kernel<<<(NROW * 128 + 255) / 256, 256>>>(y1, A3);
    dim3 fgrid(VPAD / 128, NROW / 128);
    fc_kernel<<<fgrid, 256, FC_DSMEM>>>(A3, B3, fc_b, outp);
}